// round 2
// baseline (speedup 1.0000x reference)
#include <cuda_runtime.h>
#include <cuda_bf16.h>
#include <cstdint>
#include <math.h>

#define BM 128
#define BN 128
#define BK 32
#define PAD 8
#define NTHREADS 256

// ---------------- scratch (static device allocations only) ----------------
__device__ __align__(16) __nv_bfloat16 g_hidden[1024 * 1024];
__device__ __align__(16) __nv_bfloat16 g_pT[1360 * 1024];     // pT_i is [E_i][1024]; row offsets 0,1024,1280,1344
__device__ __align__(16) __nv_bfloat16 g_proj[1024 * 1360];   // proj_i is [1024][E_i]
__device__ float g_sumExp[4 * 1024];
__device__ float g_tgtLogit[1024];
__device__ float g_clLogit[1024 * 3];
__device__ int   g_target[1024];

// ---------------- target decode: sniff int32 vs int64 layout ----------------
__global__ void decode_targets_kernel(const void* __restrict__ tptr, int n) {
    __shared__ int is64;
    if (threadIdx.x == 0) {
        // Under int64 interpretation, scan first 512 entries (= first 4KB, safe
        // even if the buffer is really int32 of n=1024 elements). If ANY value
        // is outside the valid vocab range, the buffer must be int32.
        const long long* t64 = (const long long*)tptr;
        int ok = 1;
        int lim = (n < 512) ? n : 512;
        for (int i = 0; i < lim; ++i) {
            long long v = t64[i];
            if (v < 0 || v >= 267735) { ok = 0; break; }
        }
        is64 = ok;
    }
    __syncthreads();
    for (int i = threadIdx.x; i < n; i += blockDim.x) {
        long long v = is64 ? ((const long long*)tptr)[i]
                           : (long long)((const int*)tptr)[i];
        g_target[i] = (int)v;
    }
}

// ---------------- prep: convert + transpose + zero ----------------
__global__ void prep_kernel(const float* __restrict__ hidden,
                            const float* __restrict__ p0, const float* __restrict__ p1,
                            const float* __restrict__ p2, const float* __restrict__ p3) {
    int idx = blockIdx.x * blockDim.x + threadIdx.x;
    int stride = gridDim.x * blockDim.x;
    const int NH = 1024 * 1024;
    const int NPT = 1360 * 1024;
    const int TOTAL = NH + NPT + 4096 + 1024 + 3072;
    for (int i = idx; i < TOTAL; i += stride) {
        if (i < NH) {
            g_hidden[i] = __float2bfloat16(hidden[i]);
        } else if (i < NH + NPT) {
            int j = i - NH;
            const float* p; int E; int base;
            if (j < 1024 * 1024)      { p = p0; E = 1024; base = 0; }
            else if (j < 1280 * 1024) { p = p1; E = 256;  base = 1024 * 1024; }
            else if (j < 1344 * 1024) { p = p2; E = 64;   base = 1280 * 1024; }
            else                      { p = p3; E = 16;   base = 1344 * 1024; }
            int loc = j - base;
            int e = loc >> 10;
            int k = loc & 1023;
            g_pT[j] = __float2bfloat16(p[k * E + e]);
        } else {
            int j = i - NH - NPT;
            if (j < 4096)      g_sumExp[j] = 0.f;
            else if (j < 5120) g_tgtLogit[j - 4096] = 0.f;
            else               g_clLogit[j - 5120] = 0.f;
        }
    }
}

// ---------------- mma helper ----------------
__device__ __forceinline__ void mma16816(float c[4], const uint32_t a[4], const uint32_t b[2]) {
    asm volatile(
        "mma.sync.aligned.m16n8k16.row.col.f32.bf16.bf16.f32 "
        "{%0,%1,%2,%3}, {%4,%5,%6,%7}, {%8,%9}, {%0,%1,%2,%3};\n"
        : "+f"(c[0]), "+f"(c[1]), "+f"(c[2]), "+f"(c[3])
        : "r"(a[0]), "r"(a[1]), "r"(a[2]), "r"(a[3]), "r"(b[0]), "r"(b[1]));
}

// ---------------- GEMM: C = A[M,K](bf16) @ B^T, B rows are N-dim ----------------
template <bool LOGITS>
__global__ __launch_bounds__(NTHREADS, 2)
void gemm_kernel(const __nv_bfloat16* __restrict__ A, int K,
                 const __nv_bfloat16* __restrict__ Bb,
                 const float* __restrict__ Bf, const float* __restrict__ Bf2, int split,
                 const float* __restrict__ bias, const float* __restrict__ bias2,
                 int Nn,
                 __nv_bfloat16* __restrict__ Cout,
                 int cut_l, int cut_r, int isHead,
                 float* __restrict__ sumExp) {
    __shared__ __align__(16) __nv_bfloat16 sA[BM][BK + PAD];
    __shared__ __align__(16) __nv_bfloat16 sB[BN][BK + PAD];
    __shared__ float sBias[BN];
    __shared__ int sTgt[BM];

    const int tid = threadIdx.x;
    const int wid = tid >> 5;
    const int lane = tid & 31;
    const int gid = lane >> 2;
    const int tg = lane & 3;
    const int warp_m = wid >> 1;   // 0..3  (32-row band)
    const int warp_n = wid & 1;    // 0..1  (64-col band)
    const int m0 = blockIdx.x * BM;   // M fastest -> W-tile reuse in L2 across 8 M-CTAs
    const int n0 = blockIdx.y * BN;

    if constexpr (LOGITS) {
        if (tid < BN) {
            int vg = n0 + tid;
            float bv = 0.f;
            if (vg < Nn) bv = (vg < split) ? bias[vg] : bias2[vg - split];
            sBias[tid] = bv;
        }
        if (tid < BM) sTgt[tid] = g_target[m0 + tid];
    }

    float c[2][8][4];
#pragma unroll
    for (int mt = 0; mt < 2; ++mt)
#pragma unroll
        for (int nt = 0; nt < 8; ++nt)
#pragma unroll
            for (int j = 0; j < 4; ++j) c[mt][nt][j] = 0.f;

    for (int k0 = 0; k0 < K; k0 += BK) {
        __syncthreads();
        // ---- load A tile (bf16) : 128 x 32 ----
#pragma unroll
        for (int it = 0; it < 2; ++it) {
            int t = tid + it * NTHREADS;       // 0..511
            int row = t >> 2;
            int kc = (t & 3) << 3;             // 0,8,16,24
            int kg = k0 + kc;
            uint4 v = make_uint4(0u, 0u, 0u, 0u);
            if (kg < K) v = *reinterpret_cast<const uint4*>(A + (size_t)(m0 + row) * K + kg);
            *reinterpret_cast<uint4*>(&sA[row][kc]) = v;
        }
        // ---- load B tile ----
        if constexpr (LOGITS) {
#pragma unroll
            for (int it = 0; it < 4; ++it) {
                int t = tid + it * NTHREADS;   // 0..1023
                int row = t >> 3;
                int kc = (t & 7) << 2;         // 0..28 step 4
                int kg = k0 + kc;
                int vg = n0 + row;
                float4 f = make_float4(0.f, 0.f, 0.f, 0.f);
                if (vg < Nn && kg < K) {
                    const float* src = (vg < split) ? (Bf + (size_t)vg * K + kg)
                                                    : (Bf2 + (size_t)(vg - split) * K + kg);
                    f = *reinterpret_cast<const float4*>(src);
                }
                __nv_bfloat162* d = reinterpret_cast<__nv_bfloat162*>(&sB[row][kc]);
                d[0] = __floats2bfloat162_rn(f.x, f.y);
                d[1] = __floats2bfloat162_rn(f.z, f.w);
            }
        } else {
#pragma unroll
            for (int it = 0; it < 2; ++it) {
                int t = tid + it * NTHREADS;
                int row = t >> 2;
                int kc = (t & 3) << 3;
                int kg = k0 + kc;
                int vg = n0 + row;
                uint4 v = make_uint4(0u, 0u, 0u, 0u);
                if (vg < Nn && kg < K)
                    v = *reinterpret_cast<const uint4*>(Bb + (size_t)vg * K + kg);
                *reinterpret_cast<uint4*>(&sB[row][kc]) = v;
            }
        }
        __syncthreads();

        // ---- compute ----
#pragma unroll
        for (int kk = 0; kk < BK; kk += 16) {
            uint32_t a[2][4];
#pragma unroll
            for (int mt = 0; mt < 2; ++mt) {
                int rb = warp_m * 32 + mt * 16;
                a[mt][0] = *reinterpret_cast<const uint32_t*>(&sA[rb + gid][kk + tg * 2]);
                a[mt][1] = *reinterpret_cast<const uint32_t*>(&sA[rb + gid + 8][kk + tg * 2]);
                a[mt][2] = *reinterpret_cast<const uint32_t*>(&sA[rb + gid][kk + tg * 2 + 8]);
                a[mt][3] = *reinterpret_cast<const uint32_t*>(&sA[rb + gid + 8][kk + tg * 2 + 8]);
            }
#pragma unroll
            for (int nt = 0; nt < 8; ++nt) {
                int cb = warp_n * 64 + nt * 8;
                uint32_t b[2];
                b[0] = *reinterpret_cast<const uint32_t*>(&sB[cb + gid][kk + tg * 2]);
                b[1] = *reinterpret_cast<const uint32_t*>(&sB[cb + gid][kk + tg * 2 + 8]);
                mma16816(c[0][nt], a[0], b);
                mma16816(c[1][nt], a[1], b);
            }
        }
    }

    // ---- epilogue ----
    if constexpr (!LOGITS) {
#pragma unroll
        for (int mt = 0; mt < 2; ++mt)
#pragma unroll
            for (int nt = 0; nt < 8; ++nt)
#pragma unroll
                for (int j = 0; j < 4; ++j) {
                    int row = m0 + warp_m * 32 + mt * 16 + gid + ((j >> 1) << 3);
                    int col = n0 + warp_n * 64 + nt * 8 + tg * 2 + (j & 1);
                    if (col < Nn)
                        Cout[(size_t)row * Nn + col] = __float2bfloat16(c[mt][nt][j]);
                }
    } else {
#pragma unroll
        for (int mt = 0; mt < 2; ++mt) {
#pragma unroll
            for (int half = 0; half < 2; ++half) {
                int rloc = warp_m * 32 + mt * 16 + gid + half * 8;
                int row = m0 + rloc;
                int t = sTgt[rloc];
                float s = 0.f;
#pragma unroll
                for (int nt = 0; nt < 8; ++nt) {
#pragma unroll
                    for (int jj = 0; jj < 2; ++jj) {
                        int nloc = warp_n * 64 + nt * 8 + tg * 2 + jj;
                        int col = n0 + nloc;
                        float logit = c[mt][nt][half * 2 + jj] + sBias[nloc];
                        if (col < Nn) {
                            s += __expf(logit);
                            if (t >= cut_l && t < cut_r && (t - cut_l) == col)
                                g_tgtLogit[row] = logit;
                            if (isHead && col >= Nn - 3)
                                g_clLogit[row * 3 + (col - (Nn - 3))] = logit;
                        }
                    }
                }
                s += __shfl_xor_sync(0xffffffffu, s, 1);
                s += __shfl_xor_sync(0xffffffffu, s, 2);
                if (tg == 0) atomicAdd(&sumExp[row], s);
            }
        }
    }
}

// ---------------- final NLL ----------------
__global__ void final_kernel(float* __restrict__ out) {
    int n = blockIdx.x * blockDim.x + threadIdx.x;
    if (n >= 1024) return;
    int t = g_target[n];
    int c = (t < 19997) ? 0 : (t < 39997) ? 1 : (t < 199997) ? 2 : 3;
    float head_lse = logf(g_sumExp[n]);
    float nll;
    if (c == 0) {
        nll = head_lse - g_tgtLogit[n];
    } else {
        float tail_lse = logf(g_sumExp[c * 1024 + n]);
        nll = head_lse - g_clLogit[n * 3 + (c - 1)] + tail_lse - g_tgtLogit[n];
    }
    out[n] = nll;
}

// ---------------- launch ----------------
extern "C" void kernel_launch(void* const* d_in, const int* in_sizes, int n_in,
                              void* d_out, int out_size) {
    const float* hidden = (const float*)d_in[0];
    const void*  target = (const void*)d_in[1];
    const float* W0 = (const float*)d_in[2];
    const float* b0 = (const float*)d_in[3];
    const float* p0 = (const float*)d_in[4];
    const float* W1 = (const float*)d_in[5];
    const float* b1 = (const float*)d_in[6];
    const float* p1 = (const float*)d_in[7];
    const float* W2 = (const float*)d_in[8];
    const float* b2 = (const float*)d_in[9];
    const float* p2 = (const float*)d_in[10];
    const float* W3 = (const float*)d_in[11];
    const float* b3 = (const float*)d_in[12];
    const float* p3 = (const float*)d_in[13];
    const float* cw = (const float*)d_in[14];
    const float* cb = (const float*)d_in[15];
    float* out = (float*)d_out;

    decode_targets_kernel<<<1, 256>>>(target, 1024);
    prep_kernel<<<4096, 256>>>(hidden, p0, p1, p2, p3);

    __nv_bfloat16 *dh, *dpT, *dproj;
    float* dsum;
    cudaGetSymbolAddress((void**)&dh, g_hidden);
    cudaGetSymbolAddress((void**)&dpT, g_pT);
    cudaGetSymbolAddress((void**)&dproj, g_proj);
    cudaGetSymbolAddress((void**)&dsum, g_sumExp);

    const int Es[4] = {1024, 256, 64, 16};
    const size_t pTrow[4] = {0, 1024, 1280, 1344};
    const size_t projoff[4] = {0, 1048576, 1310720, 1376256};
    const int BIG = 1 << 30;

    // projections: proj_i = hidden @ p_i
    for (int i = 0; i < 4; ++i) {
        dim3 grid(8, (Es[i] + BN - 1) / BN);
        gemm_kernel<false><<<grid, NTHREADS>>>(
            dh, 1024, dpT + pTrow[i] * 1024,
            nullptr, nullptr, BIG, nullptr, nullptr, Es[i],
            dproj + projoff[i], 0, 0, 0, nullptr);
    }

    // head cluster: W = [W0 ; cluster_weight], V = 20000
    {
        dim3 grid(8, (20000 + BN - 1) / BN);
        gemm_kernel<true><<<grid, NTHREADS>>>(
            dproj, 1024, nullptr,
            W0, cw, 19997, b0, cb, 20000,
            nullptr, 0, 19997, 1, dsum);
    }
    // tails
    const float* Ws[3] = {W1, W2, W3};
    const float* bs[3] = {b1, b2, b3};
    const int Vs[3] = {20000, 160000, 67738};
    const int cuts[5] = {0, 19997, 39997, 199997, 267735};
    for (int i = 1; i <= 3; ++i) {
        dim3 grid(8, (Vs[i - 1] + BN - 1) / BN);
        gemm_kernel<true><<<grid, NTHREADS>>>(
            dproj + projoff[i], Es[i], nullptr,
            Ws[i - 1], Ws[i - 1], BIG, bs[i - 1], bs[i - 1], Vs[i - 1],
            nullptr, cuts[i], cuts[i + 1], 0, dsum + i * 1024);
    }

    final_kernel<<<4, 256>>>(out);
}

// round 3
// speedup vs baseline: 1.9930x; 1.9930x over previous
#include <cuda_runtime.h>
#include <cuda_bf16.h>
#include <cstdint>
#include <math.h>

#define BM 128
#define BN 128
#define BK 32
#define ROWB 80               // (BK+8)*2 bytes per smem row (pad kills LDSM conflicts)
#define STAGE_BYTES 20480     // (BM+BN)*ROWB
#define SM_BIAS 61440
#define SM_TGT  61952
#define SMEM_TOTAL 62464
#define NTHREADS 256

// ---------------- static scratch ----------------
__device__ __align__(16) __nv_bfloat16 g_hidden[1024 * 1024];
__device__ __align__(16) __nv_bfloat16 g_pT[1360 * 1024];     // [1360][1024]
__device__ __align__(16) __nv_bfloat16 g_proj[1024 * 1360];   // [1024][1360]
__device__ __align__(16) __nv_bfloat16 g_Wb[36923808];        // head(20000x1024) W1(20000x256) W2(160000x64) W3(67738x16)
__device__ float g_biasHead[20000];
__device__ float g_sumExp[4 * 1024];
__device__ float g_tgtLogit[1024];
__device__ float g_clLogit[1024 * 3];
__device__ int   g_target[1024];

// ---------------- target decode (int32 vs int64 sniff, parallel) ----------------
__global__ void decode_targets_kernel(const void* __restrict__ tptr, int n) {
    __shared__ int bad;
    if (threadIdx.x == 0) bad = 0;
    __syncthreads();
    const long long* t64 = (const long long*)tptr;
    int lim = (n < 512) ? n : 512;   // first 4KB: safe under either layout
    for (int i = threadIdx.x; i < lim; i += blockDim.x) {
        long long v = t64[i];
        if (v < 0 || v >= 267735) atomicExch(&bad, 1);
    }
    __syncthreads();
    int is64 = !bad;
    for (int i = threadIdx.x; i < n; i += blockDim.x)
        g_target[i] = is64 ? (int)t64[i] : ((const int*)tptr)[i];
}

// ---------------- prep: converts, transpose, bias concat, zero ----------------
__global__ void prep_kernel(const float* __restrict__ hidden,
                            const float* __restrict__ p0, const float* __restrict__ p1,
                            const float* __restrict__ p2, const float* __restrict__ p3,
                            const float* __restrict__ W0, const float* __restrict__ cw,
                            const float* __restrict__ W1, const float* __restrict__ W2,
                            const float* __restrict__ W3,
                            const float* __restrict__ b0, const float* __restrict__ cb) {
    const int U_H  = 262144;        // hidden, x4
    const int U_W  = 9230952;       // weights, x4
    const int U_PT = 1392640;       // pT transpose, scalar
    const int U_B  = 20000;         // head bias concat
    const int U_Z  = 8192;          // zero accumulators
    const int TOTAL = U_H + U_W + U_PT + U_B + U_Z;
    int idx = blockIdx.x * blockDim.x + threadIdx.x;
    int stride = gridDim.x * blockDim.x;
    for (int u = idx; u < TOTAL; u += stride) {
        if (u < U_H) {
            int e = u * 4;
            float4 f = *reinterpret_cast<const float4*>(hidden + e);
            __nv_bfloat162 lo = __floats2bfloat162_rn(f.x, f.y);
            __nv_bfloat162 hi = __floats2bfloat162_rn(f.z, f.w);
            *reinterpret_cast<uint2*>(g_hidden + e) =
                make_uint2(*(uint32_t*)&lo, *(uint32_t*)&hi);
        } else if (u < U_H + U_W) {
            int e = (u - U_H) * 4;
            const float* src;
            if (e < 20480000)       src = (e < 20476928) ? W0 + e : cw + (e - 20476928);
            else if (e < 25600000)  src = W1 + (e - 20480000);
            else if (e < 35840000)  src = W2 + (e - 25600000);
            else                    src = W3 + (e - 35840000);
            float4 f = *reinterpret_cast<const float4*>(src);
            __nv_bfloat162 lo = __floats2bfloat162_rn(f.x, f.y);
            __nv_bfloat162 hi = __floats2bfloat162_rn(f.z, f.w);
            *reinterpret_cast<uint2*>(g_Wb + e) =
                make_uint2(*(uint32_t*)&lo, *(uint32_t*)&hi);
        } else if (u < U_H + U_W + U_PT) {
            int j = u - U_H - U_W;
            const float* p; int E; int base;
            if (j < 1024 * 1024)      { p = p0; E = 1024; base = 0; }
            else if (j < 1280 * 1024) { p = p1; E = 256;  base = 1024 * 1024; }
            else if (j < 1344 * 1024) { p = p2; E = 64;   base = 1280 * 1024; }
            else                      { p = p3; E = 16;   base = 1344 * 1024; }
            int loc = j - base;
            int e = loc >> 10;
            int k = loc & 1023;
            g_pT[j] = __float2bfloat16(p[k * E + e]);
        } else if (u < U_H + U_W + U_PT + U_B) {
            int j = u - U_H - U_W - U_PT;
            g_biasHead[j] = (j < 19997) ? b0[j] : cb[j - 19997];
        } else {
            int j = u - U_H - U_W - U_PT - U_B;
            if (j < 4096)      g_sumExp[j] = 0.f;
            else if (j < 5120) g_tgtLogit[j - 4096] = 0.f;
            else               g_clLogit[j - 5120] = 0.f;
        }
    }
}

// ---------------- asm helpers ----------------
__device__ __forceinline__ void cpa16(uint32_t dst, const void* src, int bytes) {
    asm volatile("cp.async.cg.shared.global [%0], [%1], 16, %2;\n"
                 :: "r"(dst), "l"(src), "r"(bytes));
}
__device__ __forceinline__ void ldsm4(uint32_t& r0, uint32_t& r1, uint32_t& r2, uint32_t& r3,
                                      uint32_t addr) {
    asm volatile("ldmatrix.sync.aligned.m8n8.x4.shared.b16 {%0,%1,%2,%3}, [%4];"
                 : "=r"(r0), "=r"(r1), "=r"(r2), "=r"(r3) : "r"(addr));
}
__device__ __forceinline__ void mma16816(float c[4], const uint32_t a[4], const uint32_t b0,
                                         const uint32_t b1) {
    asm volatile(
        "mma.sync.aligned.m16n8k16.row.col.f32.bf16.bf16.f32 "
        "{%0,%1,%2,%3}, {%4,%5,%6,%7}, {%8,%9}, {%0,%1,%2,%3};\n"
        : "+f"(c[0]), "+f"(c[1]), "+f"(c[2]), "+f"(c[3])
        : "r"(a[0]), "r"(a[1]), "r"(a[2]), "r"(a[3]), "r"(b0), "r"(b1));
}

// ---------------- pipelined GEMM: C = A[M,K] @ B^T  (B rows = N dim, bf16) ----------------
// LOGITS=false: write bf16 C (projection).   LOGITS=true: fused softmax-statistics epilogue.
template <bool LOGITS>
__global__ __launch_bounds__(NTHREADS, 2)
void gemm_kernel(const __nv_bfloat16* __restrict__ A, int lda, int K,
                 const __nv_bfloat16* __restrict__ B, int Nn,
                 __nv_bfloat16* __restrict__ Cout, int ldc,
                 const float* __restrict__ bias,
                 int cut_l, int isHead, float* __restrict__ sumExp) {
    extern __shared__ __align__(16) char smem[];
    uint32_t sbase = (uint32_t)__cvta_generic_to_shared(smem);
    float* sBias = (float*)(smem + SM_BIAS);
    int*   sTgt  = (int*)(smem + SM_TGT);

    const int tid = threadIdx.x;
    const int lane = tid & 31, wid = tid >> 5;
    const int gid = lane >> 2, tg = lane & 3;
    const int warp_m = wid >> 1, warp_n = wid & 1;
    const int m0 = blockIdx.x * BM;      // x fastest: 8 M-CTAs share a W tile in L2
    const int n0 = blockIdx.y * BN;

    if constexpr (LOGITS) {
        if (tid < BN) { int vg = n0 + tid; sBias[tid] = (vg < Nn) ? bias[vg] : 0.f; }
        if (tid < BM) sTgt[tid] = g_target[m0 + tid];
    }

    // cp.async mapping: 2 A-chunks + 2 B-chunks (16B) per thread per tile
    const int chA = tid & 3;
    const int rA0 = tid >> 2;

    const int ntiles = (K + BK - 1) / BK;

    auto issue = [&](int kt, int sb) {
        int k0 = kt * BK;
        uint32_t sA = sbase + sb * STAGE_BYTES;
        uint32_t sB = sA + BM * ROWB;
        int kg = k0 + chA * 8;
        bool okk = (kg < K);
#pragma unroll
        for (int it = 0; it < 2; ++it) {
            int row = rA0 + it * 64;
            const __nv_bfloat16* src = A + (size_t)(m0 + row) * lda + (okk ? kg : 0);
            cpa16(sA + row * ROWB + chA * 16, src, okk ? 16 : 0);
        }
#pragma unroll
        for (int it = 0; it < 2; ++it) {
            int row = rA0 + it * 64;
            int vg = n0 + row;
            bool ok = (vg < Nn) && okk;
            const __nv_bfloat16* src = B + (size_t)(ok ? vg : 0) * K + (ok ? kg : 0);
            cpa16(sB + row * ROWB + chA * 16, src, ok ? 16 : 0);
        }
    };

    // ldmatrix lane address bases
    const int li = lane & 7, lq = lane >> 3;
    uint32_t aAddr[2], bAddr[4];
#pragma unroll
    for (int mt = 0; mt < 2; ++mt) {
        int row = warp_m * 32 + mt * 16 + (lq & 1) * 8 + li;
        aAddr[mt] = sbase + row * ROWB + ((lq >> 1) * 8) * 2;
    }
#pragma unroll
    for (int np = 0; np < 4; ++np) {
        int row = warp_n * 64 + np * 16 + (lq >> 1) * 8 + li;
        bAddr[np] = sbase + BM * ROWB + row * ROWB + ((lq & 1) * 8) * 2;
    }

    float c[2][8][4];
#pragma unroll
    for (int mt = 0; mt < 2; ++mt)
#pragma unroll
        for (int nt = 0; nt < 8; ++nt)
#pragma unroll
            for (int j = 0; j < 4; ++j) c[mt][nt][j] = 0.f;

    // prologue: 2 stages
    if (0 < ntiles) issue(0, 0);
    asm volatile("cp.async.commit_group;\n");
    if (1 < ntiles) issue(1, 1);
    asm volatile("cp.async.commit_group;\n");

    for (int it = 0; it < ntiles; ++it) {
        asm volatile("cp.async.wait_group 1;\n");
        __syncthreads();
        int nt_tile = it + 2;
        if (nt_tile < ntiles) {
            int sb = nt_tile - (nt_tile / 3) * 3;
            issue(nt_tile, sb);
        }
        asm volatile("cp.async.commit_group;\n");

        uint32_t so = (uint32_t)(it - (it / 3) * 3) * STAGE_BYTES;
#pragma unroll
        for (int kk = 0; kk < 2; ++kk) {
            uint32_t a[2][4], b[4][4];
            ldsm4(a[0][0], a[0][1], a[0][2], a[0][3], aAddr[0] + so + kk * 32);
            ldsm4(a[1][0], a[1][1], a[1][2], a[1][3], aAddr[1] + so + kk * 32);
#pragma unroll
            for (int np = 0; np < 4; ++np)
                ldsm4(b[np][0], b[np][1], b[np][2], b[np][3], bAddr[np] + so + kk * 32);
#pragma unroll
            for (int mt = 0; mt < 2; ++mt)
#pragma unroll
                for (int nt = 0; nt < 8; ++nt)
                    mma16816(c[mt][nt], a[mt], b[nt >> 1][(nt & 1) * 2],
                             b[nt >> 1][(nt & 1) * 2 + 1]);
        }
    }

    // ---------------- epilogue ----------------
    if constexpr (!LOGITS) {
#pragma unroll
        for (int mt = 0; mt < 2; ++mt)
#pragma unroll
            for (int nt = 0; nt < 8; ++nt)
#pragma unroll
                for (int j2 = 0; j2 < 2; ++j2) {
                    int row = m0 + warp_m * 32 + mt * 16 + gid + j2 * 8;
                    int col = n0 + warp_n * 64 + nt * 8 + tg * 2;
                    if (col + 1 < Nn) {
                        __nv_bfloat162 v = __floats2bfloat162_rn(c[mt][nt][j2 * 2],
                                                                 c[mt][nt][j2 * 2 + 1]);
                        *reinterpret_cast<__nv_bfloat162*>(Cout + (size_t)row * ldc + col) = v;
                    } else if (col < Nn) {
                        Cout[(size_t)row * ldc + col] = __float2bfloat16(c[mt][nt][j2 * 2]);
                    }
                }
    } else {
        const bool edge = (n0 + BN > Nn);
#pragma unroll
        for (int mt = 0; mt < 2; ++mt) {
#pragma unroll
            for (int half = 0; half < 2; ++half) {
                int rloc = warp_m * 32 + mt * 16 + gid + half * 8;
                int row = m0 + rloc;
                int tcol = sTgt[rloc] - cut_l - n0;   // target col rel to this tile (may be OOR)
                float s = 0.f;
#pragma unroll
                for (int nt = 0; nt < 8; ++nt) {
#pragma unroll
                    for (int jj = 0; jj < 2; ++jj) {
                        int nloc = warp_n * 64 + nt * 8 + tg * 2 + jj;
                        float logit = c[mt][nt][half * 2 + jj] + sBias[nloc];
                        bool valid = !edge || (n0 + nloc < Nn);
                        if (valid) {
                            s += __expf(logit);
                            if (nloc == tcol) g_tgtLogit[row] = logit;
                            if (isHead && n0 + nloc >= Nn - 3)
                                g_clLogit[row * 3 + (n0 + nloc - (Nn - 3))] = logit;
                        }
                    }
                }
                s += __shfl_xor_sync(0xffffffffu, s, 1);
                s += __shfl_xor_sync(0xffffffffu, s, 2);
                if (tg == 0) atomicAdd(&sumExp[row], s);
            }
        }
    }
}

// ---------------- final NLL ----------------
__global__ void final_kernel(float* __restrict__ out) {
    int n = blockIdx.x * blockDim.x + threadIdx.x;
    if (n >= 1024) return;
    int t = g_target[n];
    int c = (t < 19997) ? 0 : (t < 39997) ? 1 : (t < 199997) ? 2 : 3;
    float head_lse = logf(g_sumExp[n]);
    float nll;
    if (c == 0) {
        nll = head_lse - g_tgtLogit[n];
    } else {
        float tail_lse = logf(g_sumExp[c * 1024 + n]);
        nll = head_lse - g_clLogit[n * 3 + (c - 1)] + tail_lse - g_tgtLogit[n];
    }
    out[n] = nll;
}

// ---------------- launch ----------------
extern "C" void kernel_launch(void* const* d_in, const int* in_sizes, int n_in,
                              void* d_out, int out_size) {
    const float* hidden = (const float*)d_in[0];
    const void*  target = (const void*)d_in[1];
    const float* W0 = (const float*)d_in[2];
    const float* b0 = (const float*)d_in[3];
    const float* p0 = (const float*)d_in[4];
    const float* W1 = (const float*)d_in[5];
    const float* b1 = (const float*)d_in[6];
    const float* p1 = (const float*)d_in[7];
    const float* W2 = (const float*)d_in[8];
    const float* b2 = (const float*)d_in[9];
    const float* p2 = (const float*)d_in[10];
    const float* W3 = (const float*)d_in[11];
    const float* b3 = (const float*)d_in[12];
    const float* p3 = (const float*)d_in[13];
    const float* cw = (const float*)d_in[14];
    const float* cb = (const float*)d_in[15];
    float* out = (float*)d_out;

    cudaFuncSetAttribute(gemm_kernel<false>, cudaFuncAttributeMaxDynamicSharedMemorySize, SMEM_TOTAL);
    cudaFuncSetAttribute(gemm_kernel<true>,  cudaFuncAttributeMaxDynamicSharedMemorySize, SMEM_TOTAL);

    decode_targets_kernel<<<1, 256>>>(target, 1024);
    prep_kernel<<<2048, 256>>>(hidden, p0, p1, p2, p3, W0, cw, W1, W2, W3, b0, cb);

    __nv_bfloat16 *dh, *dpT, *dproj, *dWb;
    float *dsum, *dbh;
    cudaGetSymbolAddress((void**)&dh, g_hidden);
    cudaGetSymbolAddress((void**)&dpT, g_pT);
    cudaGetSymbolAddress((void**)&dproj, g_proj);
    cudaGetSymbolAddress((void**)&dWb, g_Wb);
    cudaGetSymbolAddress((void**)&dsum, g_sumExp);
    cudaGetSymbolAddress((void**)&dbh, g_biasHead);

    // fused projection: proj[1024][1360] = hidden @ pT^T
    gemm_kernel<false><<<dim3(8, 11), NTHREADS, SMEM_TOTAL>>>(
        dh, 1024, 1024, dpT, 1360, dproj, 1360, nullptr, 0, 0, nullptr);

    // head: V=20000 (19997 shortlist + 3 cluster), K=1024
    gemm_kernel<true><<<dim3(8, 157), NTHREADS, SMEM_TOTAL>>>(
        dproj, 1360, 1024, dWb, 20000, nullptr, 0, dbh, 0, 1, dsum);
    // tail1: V=20000, K=256
    gemm_kernel<true><<<dim3(8, 157), NTHREADS, SMEM_TOTAL>>>(
        dproj + 1024, 1360, 256, dWb + 20480000, 20000, nullptr, 0, b1, 19997, 0, dsum + 1024);
    // tail2: V=160000, K=64
    gemm_kernel<true><<<dim3(8, 1250), NTHREADS, SMEM_TOTAL>>>(
        dproj + 1280, 1360, 64, dWb + 25600000, 160000, nullptr, 0, b2, 39997, 0, dsum + 2048);
    // tail3: V=67738, K=16
    gemm_kernel<true><<<dim3(8, 530), NTHREADS, SMEM_TOTAL>>>(
        dproj + 1344, 1360, 16, dWb + 35840000, 67738, nullptr, 0, b3, 199997, 0, dsum + 3072);

    final_kernel<<<4, 256>>>(out);
}